// round 11
// baseline (speedup 1.0000x reference)
#include <cuda_runtime.h>
#include <cstdint>

// 2x2 Haar DWT, fp32.
// Input:  x  (16, 1, 2048, 2048)  -> 64M floats
// Output: [ll | lh | hl | hh], each (16, 1, 1024, 1024), concatenated -> 64M floats
//
// ll = 0.5*( a + b + c + d)
// lh = 0.5*(-a + b - c + d)
// hl = 0.5*(-a - b + c + d)
// hh = 0.5*( a - b - c + d)
// _safe(): non-finite -> 0 on inputs and outputs.
//
// R9: persistent grid-stride kernel. Same per-iteration memory pattern as the
// best 74.75us kernel (one block == one output row; 4 cols/thread; 32B warp
// stride loads; 512B/warp contiguous per-subband stores), but 1184 resident
// CTAs loop over all 16384 rows — removes ~18 wave transitions and 16384x
// per-CTA prologue, keeping the LSU continuously fed.

static constexpr int B   = 16;
static constexpr int H   = 2048;
static constexpr int W   = 2048;
static constexpr int OH  = H / 2;   // 1024
static constexpr int OW  = W / 2;   // 1024
static constexpr long long SUB_ELEMS = (long long)B * OH * OW;  // 16M per subband
static constexpr int NUM_ROWS = B * OH;                         // 16384 output rows

__device__ __forceinline__ float safef(float v) {
    // finite check via exponent bits (robust under fast-math)
    return ((__float_as_uint(v) & 0x7f800000u) == 0x7f800000u) ? 0.0f : v;
}

__device__ __forceinline__ float4 safe4(float4 v) {
    v.x = safef(v.x); v.y = safef(v.y); v.z = safef(v.z); v.w = safef(v.w);
    return v;
}

__global__ __launch_bounds__(256)
void dwt2d_haar_kernel(const float* __restrict__ x, float* __restrict__ out) {
    const int g = threadIdx.x;            // col group 0..255 (4 cols each)

    for (int rn = blockIdx.x; rn < NUM_ROWS; rn += gridDim.x) {
        const int r = rn & (OH - 1);
        const int n = rn >> 10;

        const long long in_base  = (long long)n * H * W + (long long)(2 * r) * W + 8 * g;
        const float4* row0 = (const float4*)(x + in_base);
        const float4* row1 = (const float4*)(x + in_base + W);

        float4 p0 = safe4(row0[0]);   // a0 b0 a1 b1
        float4 p1 = safe4(row0[1]);   // a2 b2 a3 b3
        float4 q0 = safe4(row1[0]);   // c0 d0 c1 d1
        float4 q1 = safe4(row1[1]);   // c2 d2 c3 d3

        float a[4] = {p0.x, p0.z, p1.x, p1.z};
        float b[4] = {p0.y, p0.w, p1.y, p1.w};
        float c[4] = {q0.x, q0.z, q1.x, q1.z};
        float d[4] = {q0.y, q0.w, q1.y, q1.w};

        float4 ll, lh, hl, hh;
        float* llp = &ll.x; float* lhp = &lh.x; float* hlp = &hl.x; float* hhp = &hh.x;
#pragma unroll
        for (int i = 0; i < 4; i++) {
            float s_ab = a[i] + b[i];
            float d_ab = b[i] - a[i];
            float s_cd = c[i] + d[i];
            float d_cd = d[i] - c[i];
            llp[i] = safef(0.5f * (s_ab + s_cd));
            lhp[i] = safef(0.5f * (d_ab + d_cd));
            hlp[i] = safef(0.5f * (s_cd - s_ab));
            hhp[i] = safef(0.5f * (d_cd - d_ab));
        }

        const long long out_base = (long long)n * OH * OW + (long long)r * OW + 4 * g;
        float4* o_ll = (float4*)(out + out_base);
        float4* o_lh = (float4*)(out + out_base + SUB_ELEMS);
        float4* o_hl = (float4*)(out + out_base + 2 * SUB_ELEMS);
        float4* o_hh = (float4*)(out + out_base + 3 * SUB_ELEMS);
        __stcs(o_ll, ll);
        __stcs(o_lh, lh);
        __stcs(o_hl, hl);
        __stcs(o_hh, hh);
    }
}

extern "C" void kernel_launch(void* const* d_in, const int* in_sizes, int n_in,
                              void* d_out, int out_size) {
    const float* x = (const float*)d_in[0];
    float* out = (float*)d_out;
    const int block = 256;
    const int grid = 148 * 8;   // 1184 persistent CTAs (8 blocks x 8 warps = 64 warps/SM)
    dwt2d_haar_kernel<<<grid, block>>>(x, out);
}

// round 12
// speedup vs baseline: 1.1330x; 1.1330x over previous
#include <cuda_runtime.h>
#include <cstdint>

// 2x2 Haar DWT, fp32.
// Input:  x  (16, 1, 2048, 2048)  -> 64M floats
// Output: [ll | lh | hl | hh], each (16, 1, 1024, 1024), concatenated -> 64M floats
//
// ll = 0.5*( a + b + c + d)
// lh = 0.5*(-a + b - c + d)
// hl = 0.5*(-a - b + c + d)
// hh = 0.5*( a - b - c + d)
// _safe(): non-finite -> 0 on inputs and outputs.
//
// R12: best-known shape (R3: 4 output cols/thread, 16384 CTAs x 256 thr,
// 74.75us, DRAM 81.3%) + streaming hints on BOTH sides now:
// __ldcs loads (read-once input, evict-first) and __stcs stores (write-once
// output). Single variable vs the 74.75us kernel: load cache policy.

static constexpr int B   = 16;
static constexpr int H   = 2048;
static constexpr int W   = 2048;
static constexpr int OH  = H / 2;   // 1024
static constexpr int OW  = W / 2;   // 1024
static constexpr long long SUB_ELEMS = (long long)B * OH * OW;  // 16M per subband

__device__ __forceinline__ float safef(float v) {
    // finite check via exponent bits (robust under fast-math)
    return ((__float_as_uint(v) & 0x7f800000u) == 0x7f800000u) ? 0.0f : v;
}

__device__ __forceinline__ float4 safe4(float4 v) {
    v.x = safef(v.x); v.y = safef(v.y); v.z = safef(v.z); v.w = safef(v.w);
    return v;
}

__global__ __launch_bounds__(256)
void dwt2d_haar_kernel(const float* __restrict__ x, float* __restrict__ out) {
    // Each thread: 4 output columns of one output row.
    // Total threads = B * OH * (OW/4) = 16 * 1024 * 256 = 4,194,304
    const int t = blockIdx.x * blockDim.x + threadIdx.x;
    const int groups_per_row = OW / 4;                    // 256
    const int g = t & (groups_per_row - 1);               // col group
    const int rn = t >> 8;                                // r + n*OH combined
    const int r = rn & (OH - 1);
    const int n = rn >> 10;
    if (n >= B) return;

    const long long in_base  = (long long)n * H * W + (long long)(2 * r) * W + 8 * g;
    const float4* row0 = (const float4*)(x + in_base);
    const float4* row1 = (const float4*)(x + in_base + W);

    // Front-batched streaming loads (read-once data, evict-first in L2)
    float4 p0 = __ldcs(row0 + 0);   // a0 b0 a1 b1
    float4 p1 = __ldcs(row0 + 1);   // a2 b2 a3 b3
    float4 q0 = __ldcs(row1 + 0);   // c0 d0 c1 d1
    float4 q1 = __ldcs(row1 + 1);   // c2 d2 c3 d3
    p0 = safe4(p0); p1 = safe4(p1); q0 = safe4(q0); q1 = safe4(q1);

    float a[4] = {p0.x, p0.z, p1.x, p1.z};
    float b[4] = {p0.y, p0.w, p1.y, p1.w};
    float c[4] = {q0.x, q0.z, q1.x, q1.z};
    float d[4] = {q0.y, q0.w, q1.y, q1.w};

    float4 ll, lh, hl, hh;
    float* llp = &ll.x; float* lhp = &lh.x; float* hlp = &hl.x; float* hhp = &hh.x;
#pragma unroll
    for (int i = 0; i < 4; i++) {
        float s_ab = a[i] + b[i];
        float d_ab = b[i] - a[i];
        float s_cd = c[i] + d[i];
        float d_cd = d[i] - c[i];
        llp[i] = safef(0.5f * (s_ab + s_cd));
        lhp[i] = safef(0.5f * (d_ab + d_cd));
        hlp[i] = safef(0.5f * (s_cd - s_ab));
        hhp[i] = safef(0.5f * (d_cd - d_ab));
    }

    const long long out_base = (long long)n * OH * OW + (long long)r * OW + 4 * g;
    float4* o_ll = (float4*)(out + out_base);
    float4* o_lh = (float4*)(out + out_base + SUB_ELEMS);
    float4* o_hl = (float4*)(out + out_base + 2 * SUB_ELEMS);
    float4* o_hh = (float4*)(out + out_base + 3 * SUB_ELEMS);
    __stcs(o_ll, ll);
    __stcs(o_lh, lh);
    __stcs(o_hl, hl);
    __stcs(o_hh, hh);
}

extern "C" void kernel_launch(void* const* d_in, const int* in_sizes, int n_in,
                              void* d_out, int out_size) {
    const float* x = (const float*)d_in[0];
    float* out = (float*)d_out;
    const long long total_threads = (long long)B * OH * (OW / 4);  // 4,194,304
    const int block = 256;
    const int grid = (int)((total_threads + block - 1) / block);   // 16384
    dwt2d_haar_kernel<<<grid, block>>>(x, out);
}